// round 2
// baseline (speedup 1.0000x reference)
#include <cuda_runtime.h>
#include <cuda_bf16.h>

#define N_NODES 16384
#define N_EDGES 65536

// Scratch for layer-1 output (h1), 16384 x 64 f32 = 4 MB.
__device__ float g_h1[N_NODES * 64];

// ---------------------------------------------------------------------------
// k_init1: h1[n,:] = x[n,:8] @ root1[8,64] + bias1
// One warp per node; lane handles cols (lane, lane+32).
// ---------------------------------------------------------------------------
__global__ void k_init1(const float* __restrict__ x,
                        const float* __restrict__ root1,
                        const float* __restrict__ bias1) {
    __shared__ float sroot[512];
    __shared__ float sbias[64];
    int t = threadIdx.x;
    for (int k = t; k < 512; k += 256) sroot[k] = root1[k];
    if (t < 64) sbias[t] = bias1[t];
    __syncthreads();

    int warp = t >> 5, lane = t & 31;
    int n = blockIdx.x * 8 + warp;
    float acc0 = sbias[lane], acc1 = sbias[lane + 32];
    const float* xr = x + n * 8;
#pragma unroll
    for (int i = 0; i < 8; i++) {
        float xv = __ldg(xr + i);  // broadcast load
        acc0 = fmaf(xv, sroot[i * 64 + lane], acc0);
        acc1 = fmaf(xv, sroot[i * 64 + lane + 32], acc1);
    }
    g_h1[n * 64 + lane] = acc0;
    g_h1[n * 64 + lane + 32] = acc1;
}

// ---------------------------------------------------------------------------
// k_edge1: per-edge message for layer 1, scattered into h1 with atomics.
//   msg[e,o] = sum_{i<8} x[src[e],i] * relu(a0*A1[0,i*64+o] + a1*A1[1,i*64+o] + b1[i*64+o])
// One warp processes 4 edges per iteration; lane handles (o, o+32).
// NOTE: edge_index is int32 (JAX x64 disabled downgrades int64 -> int32).
// ---------------------------------------------------------------------------
#define EPB1 4
__global__ void k_edge1(const float* __restrict__ x,
                        const int* __restrict__ ei,
                        const float* __restrict__ ea,
                        const float* __restrict__ A1,
                        const float* __restrict__ b1) {
    __shared__ float4 sW[8 * 32];   // {P_o, Q_o, P_{o+32}, Q_{o+32}} for (i,o)
    __shared__ float2 sB[8 * 32];   // {B_o, B_{o+32}}
    __shared__ float  sx[8][EPB1 * 8];

    int t = threadIdx.x;
    for (int k = t; k < 256; k += 256) {
        int i = k >> 5, o = k & 31;
        sW[k] = make_float4(A1[i * 64 + o],       A1[512 + i * 64 + o],
                            A1[i * 64 + o + 32],  A1[512 + i * 64 + o + 32]);
        sB[k] = make_float2(b1[i * 64 + o], b1[i * 64 + o + 32]);
    }
    __syncthreads();

    int warp = t >> 5, lane = t & 31;
    int gw = blockIdx.x * 8 + warp;
    int nwarps = gridDim.x * 8;
    const int* src = ei;
    const int* dst = ei + N_EDGES;

    for (int g = gw; g < N_EDGES / EPB1; g += nwarps) {
        int e0 = g * EPB1;
        {   // stage x rows: lane -> (edge = lane>>3, feat = lane&7)
            int e = lane >> 3, i = lane & 7;
            int s = src[e0 + e];
            sx[warp][lane] = x[s * 8 + i];
        }
        __syncwarp();
        float a0[EPB1], a1[EPB1];
#pragma unroll
        for (int e = 0; e < EPB1; e++) {
            float2 at = *(const float2*)(ea + (size_t)(e0 + e) * 2);
            a0[e] = at.x; a1[e] = at.y;
        }
        float acc0[EPB1] = {0.f, 0.f, 0.f, 0.f};
        float acc1[EPB1] = {0.f, 0.f, 0.f, 0.f};
#pragma unroll
        for (int i = 0; i < 8; i++) {
            float4 w = sW[i * 32 + lane];
            float2 b = sB[i * 32 + lane];
#pragma unroll
            for (int e = 0; e < EPB1; e++) {
                float wl = fmaxf(fmaf(a1[e], w.y, fmaf(a0[e], w.x, b.x)), 0.f);
                float wh = fmaxf(fmaf(a1[e], w.w, fmaf(a0[e], w.z, b.y)), 0.f);
                float hv = sx[warp][e * 8 + i];
                acc0[e] = fmaf(hv, wl, acc0[e]);
                acc1[e] = fmaf(hv, wh, acc1[e]);
            }
        }
#pragma unroll
        for (int e = 0; e < EPB1; e++) {
            int d = dst[e0 + e];
            atomicAdd(&g_h1[d * 64 + lane],      acc0[e]);
            atomicAdd(&g_h1[d * 64 + lane + 32], acc1[e]);
        }
        __syncwarp();
    }
}

// ---------------------------------------------------------------------------
// k_init2: out[n,:] = h1[n,:64] @ root2[64,64] + bias2
// One warp per node; h1 row held 2 regs/lane, broadcast via shfl.
// ---------------------------------------------------------------------------
__global__ void k_init2(const float* __restrict__ root2,
                        const float* __restrict__ bias2,
                        float* __restrict__ out) {
    __shared__ float2 sR[64 * 32];  // {R[i,o], R[i,o+32]}
    __shared__ float  sb[64];
    int t = threadIdx.x;
    for (int k = t; k < 2048; k += 256) {
        int i = k >> 5, o = k & 31;
        sR[k] = make_float2(root2[i * 64 + o], root2[i * 64 + o + 32]);
    }
    if (t < 64) sb[t] = bias2[t];
    __syncthreads();

    int warp = t >> 5, lane = t & 31;
    int n = blockIdx.x * 8 + warp;
    float hlo = g_h1[n * 64 + lane];
    float hhi = g_h1[n * 64 + lane + 32];
    float acc0 = sb[lane], acc1 = sb[lane + 32];
#pragma unroll
    for (int i = 0; i < 64; i++) {
        float hv = __shfl_sync(0xffffffffu, (i < 32) ? hlo : hhi, i & 31);
        float2 r = sR[i * 32 + lane];
        acc0 = fmaf(hv, r.x, acc0);
        acc1 = fmaf(hv, r.y, acc1);
    }
    out[n * 64 + lane]      = acc0;
    out[n * 64 + lane + 32] = acc1;
}

// ---------------------------------------------------------------------------
// k_edge2: the hot kernel. Per-edge layer-2 message with on-the-fly weights:
//   msg[e,o] = sum_{i<64} h1[src[e],i] * relu(a0*A2[0,i*64+o] + a1*A2[1,i*64+o] + b2[i*64+o])
// A2/b2 cached packed in smem; 4 edges per warp-iteration amortizes weight reads.
// Dynamic smem: 32KB (sW) + 16KB (sB) + 8KB (h staging) = 57344 B.
// ---------------------------------------------------------------------------
#define EPB2 4
__global__ void k_edge2(const int* __restrict__ ei,
                        const float* __restrict__ ea,
                        const float* __restrict__ A2,
                        const float* __restrict__ b2,
                        float* __restrict__ out) {
    extern __shared__ float smem[];
    float4* sW = (float4*)smem;                          // 64*32 float4 = 32768 B
    float2* sB = (float2*)(smem + 64 * 32 * 4);          // 64*32 float2 = 16384 B
    float*  sh = smem + 64 * 32 * 4 + 64 * 32 * 2;       // 8 warps * 4 edges * 64 f32

    int t = threadIdx.x;
    for (int k = t; k < 2048; k += 256) {
        int i = k >> 5, o = k & 31;
        sW[k] = make_float4(A2[i * 64 + o],        A2[4096 + i * 64 + o],
                            A2[i * 64 + o + 32],   A2[4096 + i * 64 + o + 32]);
        sB[k] = make_float2(b2[i * 64 + o], b2[i * 64 + o + 32]);
    }
    __syncthreads();

    int warp = t >> 5, lane = t & 31;
    float* shw = sh + warp * (EPB2 * 64);
    int gw = blockIdx.x * 8 + warp;
    int nwarps = gridDim.x * 8;
    const int* src = ei;
    const int* dst = ei + N_EDGES;

    for (int g = gw; g < N_EDGES / EPB2; g += nwarps) {
        int e0 = g * EPB2;
        float a0[EPB2], a1[EPB2];
#pragma unroll
        for (int e = 0; e < EPB2; e++) {
            int s = src[e0 + e];
            // gather h1 row (256B coalesced per edge) into smem
            float2 hv = *(const float2*)(&g_h1[s * 64 + lane * 2]);
            ((float2*)shw)[e * 32 + lane] = hv;
            float2 at = *(const float2*)(ea + (size_t)(e0 + e) * 2);
            a0[e] = at.x; a1[e] = at.y;
        }
        __syncwarp();

        float acc0[EPB2] = {0.f, 0.f, 0.f, 0.f};
        float acc1[EPB2] = {0.f, 0.f, 0.f, 0.f};
#pragma unroll 4
        for (int i = 0; i < 64; i++) {
            float4 w = sW[i * 32 + lane];
            float2 b = sB[i * 32 + lane];
#pragma unroll
            for (int e = 0; e < EPB2; e++) {
                float hv = shw[e * 64 + i];  // broadcast
                float wl = fmaxf(fmaf(a1[e], w.y, fmaf(a0[e], w.x, b.x)), 0.f);
                float wh = fmaxf(fmaf(a1[e], w.w, fmaf(a0[e], w.z, b.y)), 0.f);
                acc0[e] = fmaf(hv, wl, acc0[e]);
                acc1[e] = fmaf(hv, wh, acc1[e]);
            }
        }
#pragma unroll
        for (int e = 0; e < EPB2; e++) {
            int d = dst[e0 + e];
            atomicAdd(&out[d * 64 + lane],      acc0[e]);
            atomicAdd(&out[d * 64 + lane + 32], acc1[e]);
        }
        __syncwarp();
    }
}

// ---------------------------------------------------------------------------
// Launch: init1 -> edge1 -> init2 -> edge2 (all on default stream, capturable)
// Inputs (metadata order):
//   0 x[16384,8] f32 | 1 edge_index[2,65536] i32 | 2 edge_attr[65536,2] f32
//   3 A1[2,512] | 4 b1[512] | 5 A2[2,4096] | 6 b2[4096]
//   7 root1[8,64] | 8 bias1[64] | 9 root2[64,64] | 10 bias2[64]
// ---------------------------------------------------------------------------
extern "C" void kernel_launch(void* const* d_in, const int* in_sizes, int n_in,
                              void* d_out, int out_size) {
    const float* x     = (const float*)d_in[0];
    const int*   ei    = (const int*)d_in[1];
    const float* ea    = (const float*)d_in[2];
    const float* A1    = (const float*)d_in[3];
    const float* b1    = (const float*)d_in[4];
    const float* A2    = (const float*)d_in[5];
    const float* b2    = (const float*)d_in[6];
    const float* root1 = (const float*)d_in[7];
    const float* bias1 = (const float*)d_in[8];
    const float* root2 = (const float*)d_in[9];
    const float* bias2 = (const float*)d_in[10];
    float* out = (float*)d_out;

    const int smem2 = 64 * 32 * 16 + 64 * 32 * 8 + 8 * EPB2 * 64 * 4;  // 57344
    cudaFuncSetAttribute(k_edge2, cudaFuncAttributeMaxDynamicSharedMemorySize, smem2);

    k_init1<<<N_NODES / 8, 256>>>(x, root1, bias1);
    k_edge1<<<1024, 256>>>(x, ei, ea, A1, b1);
    k_init2<<<N_NODES / 8, 256>>>(root2, bias2, out);
    k_edge2<<<592, 256, smem2>>>(ei, ea, A2, b2, out);
}

// round 3
// speedup vs baseline: 1.1413x; 1.1413x over previous
#include <cuda_runtime.h>
#include <cuda_bf16.h>

#define N_NODES 16384
#define N_EDGES 65536

// Scratch for layer-1 output (h1), 16384 x 64 f32 = 4 MB.
__device__ float g_h1[N_NODES * 64];

// ---------- packed f32x2 helpers (Blackwell FFMA2) ----------
__device__ __forceinline__ unsigned long long ffma2(unsigned long long a,
                                                    unsigned long long b,
                                                    unsigned long long c) {
    unsigned long long d;
    asm("fma.rn.f32x2 %0, %1, %2, %3;" : "=l"(d) : "l"(a), "l"(b), "l"(c));
    return d;
}
__device__ __forceinline__ unsigned long long pack2(float x, float y) {
    unsigned long long r;
    asm("mov.b64 %0, {%1, %2};" : "=l"(r) : "f"(x), "f"(y));
    return r;
}
__device__ __forceinline__ float2 unpack2(unsigned long long v) {
    float2 f;
    asm("mov.b64 {%0, %1}, %2;" : "=f"(f.x), "=f"(f.y) : "l"(v));
    return f;
}
__device__ __forceinline__ unsigned long long relu2(unsigned long long v) {
    float2 f = unpack2(v);
    f.x = fmaxf(f.x, 0.f);
    f.y = fmaxf(f.y, 0.f);
    return pack2(f.x, f.y);
}

// ---------------------------------------------------------------------------
// k_init1: h1[n,:] = x[n,:8] @ root1[8,64] + bias1. One warp per node.
// ---------------------------------------------------------------------------
__global__ void k_init1(const float* __restrict__ x,
                        const float* __restrict__ root1,
                        const float* __restrict__ bias1) {
    __shared__ float sroot[512];
    __shared__ float sbias[64];
    int t = threadIdx.x;
    for (int k = t; k < 512; k += 256) sroot[k] = root1[k];
    if (t < 64) sbias[t] = bias1[t];
    __syncthreads();

    int warp = t >> 5, lane = t & 31;
    int n = blockIdx.x * 8 + warp;
    float acc0 = sbias[lane], acc1 = sbias[lane + 32];
    const float* xr = x + n * 8;
#pragma unroll
    for (int i = 0; i < 8; i++) {
        float xv = __ldg(xr + i);
        acc0 = fmaf(xv, sroot[i * 64 + lane], acc0);
        acc1 = fmaf(xv, sroot[i * 64 + lane + 32], acc1);
    }
    g_h1[n * 64 + lane] = acc0;
    g_h1[n * 64 + lane + 32] = acc1;
}

// ---------------------------------------------------------------------------
// k_edge1: layer-1 edge messages, atomically scattered into h1.
// edge_index is int32 (JAX x64 disabled).
// ---------------------------------------------------------------------------
#define EPB1 4
__global__ void k_edge1(const float* __restrict__ x,
                        const int* __restrict__ ei,
                        const float* __restrict__ ea,
                        const float* __restrict__ A1,
                        const float* __restrict__ b1) {
    __shared__ float4 sW[8 * 32];
    __shared__ float2 sB[8 * 32];
    __shared__ float  sx[8][EPB1 * 8];

    int t = threadIdx.x;
    for (int k = t; k < 256; k += 256) {
        int i = k >> 5, o = k & 31;
        sW[k] = make_float4(A1[i * 64 + o],       A1[512 + i * 64 + o],
                            A1[i * 64 + o + 32],  A1[512 + i * 64 + o + 32]);
        sB[k] = make_float2(b1[i * 64 + o], b1[i * 64 + o + 32]);
    }
    __syncthreads();

    int warp = t >> 5, lane = t & 31;
    int gw = blockIdx.x * 8 + warp;
    int nwarps = gridDim.x * 8;
    const int* src = ei;
    const int* dst = ei + N_EDGES;

    for (int g = gw; g < N_EDGES / EPB1; g += nwarps) {
        int e0 = g * EPB1;
        {
            int e = lane >> 3, i = lane & 7;
            int s = src[e0 + e];
            sx[warp][lane] = x[s * 8 + i];
        }
        __syncwarp();
        float a0[EPB1], a1[EPB1];
#pragma unroll
        for (int e = 0; e < EPB1; e++) {
            float2 at = *(const float2*)(ea + (size_t)(e0 + e) * 2);
            a0[e] = at.x; a1[e] = at.y;
        }
        float acc0[EPB1] = {0.f, 0.f, 0.f, 0.f};
        float acc1[EPB1] = {0.f, 0.f, 0.f, 0.f};
#pragma unroll
        for (int i = 0; i < 8; i++) {
            float4 w = sW[i * 32 + lane];
            float2 b = sB[i * 32 + lane];
#pragma unroll
            for (int e = 0; e < EPB1; e++) {
                float wl = fmaxf(fmaf(a1[e], w.y, fmaf(a0[e], w.x, b.x)), 0.f);
                float wh = fmaxf(fmaf(a1[e], w.w, fmaf(a0[e], w.z, b.y)), 0.f);
                float hv = sx[warp][e * 8 + i];
                acc0[e] = fmaf(hv, wl, acc0[e]);
                acc1[e] = fmaf(hv, wh, acc1[e]);
            }
        }
#pragma unroll
        for (int e = 0; e < EPB1; e++) {
            int d = dst[e0 + e];
            atomicAdd(&g_h1[d * 64 + lane],      acc0[e]);
            atomicAdd(&g_h1[d * 64 + lane + 32], acc1[e]);
        }
        __syncwarp();
    }
}

// ---------------------------------------------------------------------------
// k_init2: out[n,:] = h1[n,:64] @ root2[64,64] + bias2. One warp per node.
// ---------------------------------------------------------------------------
__global__ void k_init2(const float* __restrict__ root2,
                        const float* __restrict__ bias2,
                        float* __restrict__ out) {
    __shared__ float2 sR[64 * 32];
    __shared__ float  sb[64];
    int t = threadIdx.x;
    for (int k = t; k < 2048; k += 256) {
        int i = k >> 5, o = k & 31;
        sR[k] = make_float2(root2[i * 64 + o], root2[i * 64 + o + 32]);
    }
    if (t < 64) sb[t] = bias2[t];
    __syncthreads();

    int warp = t >> 5, lane = t & 31;
    int n = blockIdx.x * 8 + warp;
    float hlo = g_h1[n * 64 + lane];
    float hhi = g_h1[n * 64 + lane + 32];
    float acc0 = sb[lane], acc1 = sb[lane + 32];
#pragma unroll
    for (int i = 0; i < 64; i++) {
        float hv = __shfl_sync(0xffffffffu, (i < 32) ? hlo : hhi, i & 31);
        float2 r = sR[i * 32 + lane];
        acc0 = fmaf(hv, r.x, acc0);
        acc1 = fmaf(hv, r.y, acc1);
    }
    out[n * 64 + lane]      = acc0;
    out[n * 64 + lane + 32] = acc1;
}

// ---------------------------------------------------------------------------
// k_edge2: hot kernel, packed-over-i f32x2 version.
//   msg[e,o] = sum_i h1[src[e],i] * relu(a0*P[i,o] + a1*Q[i,o] + B[i,o])
// i processed in pairs p=(2p,2p+1) with FFMA2; lane owns cols (o, o+32);
// 4 edges per warp-iteration amortize weight reads.
// smem: sWlo 16K | sWhi 16K | sBlo 8K | sBhi 8K | staging 8K = 57344 B.
// ---------------------------------------------------------------------------
#define EPB2 4
__global__ void __launch_bounds__(256)
k_edge2(const int* __restrict__ ei,
        const float* __restrict__ ea,
        const float* __restrict__ A2,
        const float* __restrict__ b2,
        float* __restrict__ out) {
    extern __shared__ float smem[];
    float4* sWlo = (float4*)smem;                       // [32p][32o] {P0,P1,Q0,Q1}
    float4* sWhi = (float4*)(smem + 4096);              // same for o+32
    float2* sBlo = (float2*)(smem + 8192);              // {B0,B1}
    float2* sBhi = (float2*)(smem + 10240);
    float*  sh   = smem + 12288;                        // 8 warps * 4 edges * 64

    int t = threadIdx.x;
    for (int k = t; k < 1024; k += 256) {
        int p = k >> 5, o = k & 31;
        int i0 = 2 * p;
        sWlo[k] = make_float4(A2[i0 * 64 + o],        A2[(i0 + 1) * 64 + o],
                              A2[4096 + i0 * 64 + o], A2[4096 + (i0 + 1) * 64 + o]);
        sWhi[k] = make_float4(A2[i0 * 64 + o + 32],        A2[(i0 + 1) * 64 + o + 32],
                              A2[4096 + i0 * 64 + o + 32], A2[4096 + (i0 + 1) * 64 + o + 32]);
        sBlo[k] = make_float2(b2[i0 * 64 + o],      b2[(i0 + 1) * 64 + o]);
        sBhi[k] = make_float2(b2[i0 * 64 + o + 32], b2[(i0 + 1) * 64 + o + 32]);
    }
    __syncthreads();

    int warp = t >> 5, lane = t & 31;
    float* shw = sh + warp * (EPB2 * 64);
    const unsigned long long* shw2 = (const unsigned long long*)shw;
    const ulonglong2* pWlo = (const ulonglong2*)sWlo;
    const ulonglong2* pWhi = (const ulonglong2*)sWhi;
    const unsigned long long* pBlo = (const unsigned long long*)sBlo;
    const unsigned long long* pBhi = (const unsigned long long*)sBhi;

    int gw = blockIdx.x * 8 + warp;
    int nwarps = gridDim.x * 8;
    const int* src = ei;
    const int* dst = ei + N_EDGES;

    for (int g = gw; g < N_EDGES / EPB2; g += nwarps) {
        int e0 = g * EPB2;
        unsigned long long a0d[EPB2], a1d[EPB2];
#pragma unroll
        for (int e = 0; e < EPB2; e++) {
            int s = src[e0 + e];
            // gather h1 row (256B coalesced) into smem, pairs over i
            float2 hv = *(const float2*)(&g_h1[s * 64 + lane * 2]);
            ((float2*)shw)[e * 32 + lane] = hv;
            float2 at = *(const float2*)(ea + (size_t)(e0 + e) * 2);
            a0d[e] = pack2(at.x, at.x);
            a1d[e] = pack2(at.y, at.y);
        }
        __syncwarp();

        unsigned long long accL[EPB2] = {0ull, 0ull, 0ull, 0ull};
        unsigned long long accH[EPB2] = {0ull, 0ull, 0ull, 0ull};
#pragma unroll 4
        for (int p = 0; p < 32; p++) {
            ulonglong2 wlo = pWlo[p * 32 + lane];   // .x = {P0,P1}, .y = {Q0,Q1}
            ulonglong2 whi = pWhi[p * 32 + lane];
            unsigned long long blo = pBlo[p * 32 + lane];
            unsigned long long bhi = pBhi[p * 32 + lane];
#pragma unroll
            for (int e = 0; e < EPB2; e++) {
                unsigned long long h2 = shw2[e * 32 + p];   // {h[2p], h[2p+1]} broadcast
                unsigned long long wl = ffma2(a0d[e], wlo.x, blo);
                wl = relu2(ffma2(a1d[e], wlo.y, wl));
                accL[e] = ffma2(h2, wl, accL[e]);
                unsigned long long wh = ffma2(a0d[e], whi.x, bhi);
                wh = relu2(ffma2(a1d[e], whi.y, wh));
                accH[e] = ffma2(h2, wh, accH[e]);
            }
        }
#pragma unroll
        for (int e = 0; e < EPB2; e++) {
            int d = dst[e0 + e];
            float2 al = unpack2(accL[e]);
            float2 ah = unpack2(accH[e]);
            atomicAdd(&out[d * 64 + lane],      al.x + al.y);
            atomicAdd(&out[d * 64 + lane + 32], ah.x + ah.y);
        }
        __syncwarp();
    }
}

// ---------------------------------------------------------------------------
// Launch: init1 -> edge1 -> init2 -> edge2 (default stream, graph-capturable).
// Inputs (metadata order):
//   0 x[16384,8] f32 | 1 edge_index[2,65536] i32 | 2 edge_attr[65536,2] f32
//   3 A1[2,512] | 4 b1[512] | 5 A2[2,4096] | 6 b2[4096]
//   7 root1[8,64] | 8 bias1[64] | 9 root2[64,64] | 10 bias2[64]
// ---------------------------------------------------------------------------
extern "C" void kernel_launch(void* const* d_in, const int* in_sizes, int n_in,
                              void* d_out, int out_size) {
    const float* x     = (const float*)d_in[0];
    const int*   ei    = (const int*)d_in[1];
    const float* ea    = (const float*)d_in[2];
    const float* A1    = (const float*)d_in[3];
    const float* b1    = (const float*)d_in[4];
    const float* A2    = (const float*)d_in[5];
    const float* b2    = (const float*)d_in[6];
    const float* root1 = (const float*)d_in[7];
    const float* bias1 = (const float*)d_in[8];
    const float* root2 = (const float*)d_in[9];
    const float* bias2 = (const float*)d_in[10];
    float* out = (float*)d_out;

    const int smem2 = 57344;
    cudaFuncSetAttribute(k_edge2, cudaFuncAttributeMaxDynamicSharedMemorySize, smem2);

    k_init1<<<N_NODES / 8, 256>>>(x, root1, bias1);
    k_edge1<<<444, 256>>>(x, ei, ea, A1, b1);
    k_init2<<<N_NODES / 8, 256>>>(root2, bias2, out);
    k_edge2<<<444, 256, smem2>>>(ei, ea, A2, b2, out);
}

// round 4
// speedup vs baseline: 1.2926x; 1.1326x over previous
#include <cuda_runtime.h>
#include <cuda_bf16.h>

#define N_NODES 16384
#define N_EDGES 65536

// Scratch for layer-1 output (h1), 16384 x 64 f32 = 4 MB.
__device__ float g_h1[N_NODES * 64];

// ---------- packed f32x2 helpers (Blackwell FFMA2) ----------
__device__ __forceinline__ unsigned long long ffma2(unsigned long long a,
                                                    unsigned long long b,
                                                    unsigned long long c) {
    unsigned long long d;
    asm("fma.rn.f32x2 %0, %1, %2, %3;" : "=l"(d) : "l"(a), "l"(b), "l"(c));
    return d;
}
__device__ __forceinline__ unsigned long long pack2(float x, float y) {
    unsigned long long r;
    asm("mov.b64 %0, {%1, %2};" : "=l"(r) : "f"(x), "f"(y));
    return r;
}
__device__ __forceinline__ float2 unpack2(unsigned long long v) {
    float2 f;
    asm("mov.b64 {%0, %1}, %2;" : "=f"(f.x), "=f"(f.y) : "l"(v));
    return f;
}
__device__ __forceinline__ unsigned long long relu2(unsigned long long v) {
    float2 f = unpack2(v);
    f.x = fmaxf(f.x, 0.f);
    f.y = fmaxf(f.y, 0.f);
    return pack2(f.x, f.y);
}

// ---------------------------------------------------------------------------
// k_init1: h1[n,:] = x[n,:8] @ root1[8,64] + bias1. One warp per node.
// ---------------------------------------------------------------------------
__global__ void k_init1(const float* __restrict__ x,
                        const float* __restrict__ root1,
                        const float* __restrict__ bias1) {
    __shared__ float sroot[512];
    __shared__ float sbias[64];
    int t = threadIdx.x;
    for (int k = t; k < 512; k += 256) sroot[k] = root1[k];
    if (t < 64) sbias[t] = bias1[t];
    __syncthreads();

    int warp = t >> 5, lane = t & 31;
    int n = blockIdx.x * 8 + warp;
    float acc0 = sbias[lane], acc1 = sbias[lane + 32];
    const float* xr = x + n * 8;
#pragma unroll
    for (int i = 0; i < 8; i++) {
        float xv = __ldg(xr + i);
        acc0 = fmaf(xv, sroot[i * 64 + lane], acc0);
        acc1 = fmaf(xv, sroot[i * 64 + lane + 32], acc1);
    }
    g_h1[n * 64 + lane] = acc0;
    g_h1[n * 64 + lane + 32] = acc1;
}

// ---------------------------------------------------------------------------
// k_edge1: layer-1 edge messages (c_in=8 -> 4 i-pairs), packed f32x2,
// 8 edges per warp-iteration, atomically scattered into h1.
// edge_index is int32 (JAX x64 disabled).
// ---------------------------------------------------------------------------
#define EPB1 8
__global__ void __launch_bounds__(256, 2)
k_edge1(const float* __restrict__ x,
        const int* __restrict__ ei,
        const float* __restrict__ ea,
        const float* __restrict__ A1,
        const float* __restrict__ b1) {
    __shared__ float4 sWlo[4 * 32];   // [p][o] {P0,P1,Q0,Q1} for cols o
    __shared__ float4 sWhi[4 * 32];   // same for o+32
    __shared__ float2 sBlo[4 * 32];   // {B0,B1}
    __shared__ float2 sBhi[4 * 32];
    __shared__ float  sx[8][EPB1 * 8];  // per warp: 8 edges x 8 feats

    int t = threadIdx.x;
    for (int k = t; k < 128; k += 256) {
        int p = k >> 5, o = k & 31;
        int i0 = 2 * p;
        sWlo[k] = make_float4(A1[i0 * 64 + o],       A1[(i0 + 1) * 64 + o],
                              A1[512 + i0 * 64 + o], A1[512 + (i0 + 1) * 64 + o]);
        sWhi[k] = make_float4(A1[i0 * 64 + o + 32],       A1[(i0 + 1) * 64 + o + 32],
                              A1[512 + i0 * 64 + o + 32], A1[512 + (i0 + 1) * 64 + o + 32]);
        sBlo[k] = make_float2(b1[i0 * 64 + o],      b1[(i0 + 1) * 64 + o]);
        sBhi[k] = make_float2(b1[i0 * 64 + o + 32], b1[(i0 + 1) * 64 + o + 32]);
    }
    __syncthreads();

    int warp = t >> 5, lane = t & 31;
    const unsigned long long* sx2 = (const unsigned long long*)sx[warp];
    const ulonglong2* pWlo = (const ulonglong2*)sWlo;
    const ulonglong2* pWhi = (const ulonglong2*)sWhi;
    const unsigned long long* pBlo = (const unsigned long long*)sBlo;
    const unsigned long long* pBhi = (const unsigned long long*)sBhi;

    int gw = blockIdx.x * 8 + warp;
    int nwarps = gridDim.x * 8;
    const int* src = ei;
    const int* dst = ei + N_EDGES;

    for (int g = gw; g < N_EDGES / EPB1; g += nwarps) {
        int e0 = g * EPB1;
        {   // stage x rows: lane -> (edge = lane>>2, float2 j = lane&3)
            int e = lane >> 2, j = lane & 3;
            int s = src[e0 + e];
            float2 v = *(const float2*)(x + (size_t)s * 8 + j * 2);
            ((float2*)sx[warp])[e * 4 + j] = v;
        }
        unsigned long long a0d[EPB1], a1d[EPB1];
#pragma unroll
        for (int e = 0; e < EPB1; e++) {
            float2 at = *(const float2*)(ea + (size_t)(e0 + e) * 2);
            a0d[e] = pack2(at.x, at.x);
            a1d[e] = pack2(at.y, at.y);
        }
        __syncwarp();

        unsigned long long accL[EPB1], accH[EPB1];
#pragma unroll
        for (int e = 0; e < EPB1; e++) { accL[e] = 0ull; accH[e] = 0ull; }
#pragma unroll
        for (int p = 0; p < 4; p++) {
            ulonglong2 wlo = pWlo[p * 32 + lane];
            ulonglong2 whi = pWhi[p * 32 + lane];
            unsigned long long blo = pBlo[p * 32 + lane];
            unsigned long long bhi = pBhi[p * 32 + lane];
#pragma unroll
            for (int e = 0; e < EPB1; e++) {
                unsigned long long h2 = sx2[e * 4 + p];
                unsigned long long wl = ffma2(a0d[e], wlo.x, blo);
                wl = relu2(ffma2(a1d[e], wlo.y, wl));
                accL[e] = ffma2(h2, wl, accL[e]);
                unsigned long long wh = ffma2(a0d[e], whi.x, bhi);
                wh = relu2(ffma2(a1d[e], whi.y, wh));
                accH[e] = ffma2(h2, wh, accH[e]);
            }
        }
#pragma unroll
        for (int e = 0; e < EPB1; e++) {
            int d = dst[e0 + e];
            float2 al = unpack2(accL[e]);
            float2 ah = unpack2(accH[e]);
            atomicAdd(&g_h1[d * 64 + lane],      al.x + al.y);
            atomicAdd(&g_h1[d * 64 + lane + 32], ah.x + ah.y);
        }
        __syncwarp();
    }
}

// ---------------------------------------------------------------------------
// k_init2: out[n,:] = h1[n,:64] @ root2[64,64] + bias2.
// 4 nodes per warp: root2 crossbar traffic amortized 4x; h rows in registers,
// broadcast via shfl.
// ---------------------------------------------------------------------------
__global__ void k_init2(const float* __restrict__ root2,
                        const float* __restrict__ bias2,
                        float* __restrict__ out) {
    __shared__ float2 sR[64 * 32];
    __shared__ float  sb[64];
    int t = threadIdx.x;
    for (int k = t; k < 2048; k += 256) {
        int i = k >> 5, o = k & 31;
        sR[k] = make_float2(root2[i * 64 + o], root2[i * 64 + o + 32]);
    }
    if (t < 64) sb[t] = bias2[t];
    __syncthreads();

    int warp = t >> 5, lane = t & 31;
    int n0 = (blockIdx.x * 8 + warp) * 4;
    float hlo[4], hhi[4], acc0[4], acc1[4];
#pragma unroll
    for (int n = 0; n < 4; n++) {
        hlo[n] = g_h1[(n0 + n) * 64 + lane];
        hhi[n] = g_h1[(n0 + n) * 64 + lane + 32];
        acc0[n] = sb[lane];
        acc1[n] = sb[lane + 32];
    }
#pragma unroll
    for (int i = 0; i < 64; i++) {
        float2 r = sR[i * 32 + lane];
#pragma unroll
        for (int n = 0; n < 4; n++) {
            float hv = __shfl_sync(0xffffffffu, (i < 32) ? hlo[n] : hhi[n], i & 31);
            acc0[n] = fmaf(hv, r.x, acc0[n]);
            acc1[n] = fmaf(hv, r.y, acc1[n]);
        }
    }
#pragma unroll
    for (int n = 0; n < 4; n++) {
        out[(n0 + n) * 64 + lane]      = acc0[n];
        out[(n0 + n) * 64 + lane + 32] = acc1[n];
    }
}

// ---------------------------------------------------------------------------
// k_edge2: hot kernel. Packed-over-i f32x2, 8 edges per warp-iteration so the
// 12 weight floats/lane/i-pair amortize over 8 edges (2.5 crossbar phases/edge).
//   msg[e,o] = sum_i h1[src[e],i] * relu(a0*P[i,o] + a1*Q[i,o] + B[i,o])
// smem: sWlo 16K | sWhi 16K | sBlo 8K | sBhi 8K | staging 16K = 65536 B.
// ---------------------------------------------------------------------------
#define EPB2 8
__global__ void __launch_bounds__(256, 2)
k_edge2(const int* __restrict__ ei,
        const float* __restrict__ ea,
        const float* __restrict__ A2,
        const float* __restrict__ b2,
        float* __restrict__ out) {
    extern __shared__ float smem[];
    float4* sWlo = (float4*)smem;                       // [32p][32o] {P0,P1,Q0,Q1}
    float4* sWhi = (float4*)(smem + 4096);              // same for o+32
    float2* sBlo = (float2*)(smem + 8192);              // {B0,B1}
    float2* sBhi = (float2*)(smem + 10240);
    float*  sh   = smem + 12288;                        // 8 warps * 8 edges * 64

    int t = threadIdx.x;
    for (int k = t; k < 1024; k += 256) {
        int p = k >> 5, o = k & 31;
        int i0 = 2 * p;
        sWlo[k] = make_float4(A2[i0 * 64 + o],        A2[(i0 + 1) * 64 + o],
                              A2[4096 + i0 * 64 + o], A2[4096 + (i0 + 1) * 64 + o]);
        sWhi[k] = make_float4(A2[i0 * 64 + o + 32],        A2[(i0 + 1) * 64 + o + 32],
                              A2[4096 + i0 * 64 + o + 32], A2[4096 + (i0 + 1) * 64 + o + 32]);
        sBlo[k] = make_float2(b2[i0 * 64 + o],      b2[(i0 + 1) * 64 + o]);
        sBhi[k] = make_float2(b2[i0 * 64 + o + 32], b2[(i0 + 1) * 64 + o + 32]);
    }
    __syncthreads();

    int warp = t >> 5, lane = t & 31;
    float* shw = sh + warp * (EPB2 * 64);
    const unsigned long long* shw2 = (const unsigned long long*)shw;
    const ulonglong2* pWlo = (const ulonglong2*)sWlo;
    const ulonglong2* pWhi = (const ulonglong2*)sWhi;
    const unsigned long long* pBlo = (const unsigned long long*)sBlo;
    const unsigned long long* pBhi = (const unsigned long long*)sBhi;

    int gw = blockIdx.x * 8 + warp;
    int nwarps = gridDim.x * 8;
    const int* src = ei;
    const int* dst = ei + N_EDGES;

    for (int g = gw; g < N_EDGES / EPB2; g += nwarps) {
        int e0 = g * EPB2;
        unsigned long long a0d[EPB2], a1d[EPB2];
#pragma unroll
        for (int e = 0; e < EPB2; e++) {
            int s = src[e0 + e];
            // gather h1 row (256B coalesced) into smem, pairs over i
            float2 hv = *(const float2*)(&g_h1[s * 64 + lane * 2]);
            ((float2*)shw)[e * 32 + lane] = hv;
            float2 at = *(const float2*)(ea + (size_t)(e0 + e) * 2);
            a0d[e] = pack2(at.x, at.x);
            a1d[e] = pack2(at.y, at.y);
        }
        __syncwarp();

        unsigned long long accL[EPB2], accH[EPB2];
#pragma unroll
        for (int e = 0; e < EPB2; e++) { accL[e] = 0ull; accH[e] = 0ull; }
#pragma unroll 4
        for (int p = 0; p < 32; p++) {
            ulonglong2 wlo = pWlo[p * 32 + lane];   // .x = {P0,P1}, .y = {Q0,Q1}
            ulonglong2 whi = pWhi[p * 32 + lane];
            unsigned long long blo = pBlo[p * 32 + lane];
            unsigned long long bhi = pBhi[p * 32 + lane];
#pragma unroll
            for (int e = 0; e < EPB2; e++) {
                unsigned long long h2 = shw2[e * 32 + p];   // {h[2p], h[2p+1]} broadcast
                unsigned long long wl = ffma2(a0d[e], wlo.x, blo);
                wl = relu2(ffma2(a1d[e], wlo.y, wl));
                accL[e] = ffma2(h2, wl, accL[e]);
                unsigned long long wh = ffma2(a0d[e], whi.x, bhi);
                wh = relu2(ffma2(a1d[e], whi.y, wh));
                accH[e] = ffma2(h2, wh, accH[e]);
            }
        }
#pragma unroll
        for (int e = 0; e < EPB2; e++) {
            int d = dst[e0 + e];
            float2 al = unpack2(accL[e]);
            float2 ah = unpack2(accH[e]);
            atomicAdd(&out[d * 64 + lane],      al.x + al.y);
            atomicAdd(&out[d * 64 + lane + 32], ah.x + ah.y);
        }
        __syncwarp();
    }
}

// ---------------------------------------------------------------------------
// Launch: init1 -> edge1 -> init2 -> edge2 (default stream, graph-capturable).
// Inputs (metadata order):
//   0 x[16384,8] f32 | 1 edge_index[2,65536] i32 | 2 edge_attr[65536,2] f32
//   3 A1[2,512] | 4 b1[512] | 5 A2[2,4096] | 6 b2[4096]
//   7 root1[8,64] | 8 bias1[64] | 9 root2[64,64] | 10 bias2[64]
// ---------------------------------------------------------------------------
extern "C" void kernel_launch(void* const* d_in, const int* in_sizes, int n_in,
                              void* d_out, int out_size) {
    const float* x     = (const float*)d_in[0];
    const int*   ei    = (const int*)d_in[1];
    const float* ea    = (const float*)d_in[2];
    const float* A1    = (const float*)d_in[3];
    const float* b1    = (const float*)d_in[4];
    const float* A2    = (const float*)d_in[5];
    const float* b2    = (const float*)d_in[6];
    const float* root1 = (const float*)d_in[7];
    const float* bias1 = (const float*)d_in[8];
    const float* root2 = (const float*)d_in[9];
    const float* bias2 = (const float*)d_in[10];
    float* out = (float*)d_out;

    const int smem2 = 65536;
    cudaFuncSetAttribute(k_edge2, cudaFuncAttributeMaxDynamicSharedMemorySize, smem2);

    k_init1<<<N_NODES / 8, 256>>>(x, root1, bias1);
    k_edge1<<<296, 256>>>(x, ei, ea, A1, b1);
    k_init2<<<N_NODES / 32, 256>>>(root2, bias2, out);
    k_edge2<<<296, 256, smem2>>>(ei, ea, A2, b2, out);
}